// round 10
// baseline (speedup 1.0000x reference)
#include <cuda_runtime.h>

#define HH 256
#define WW 256
#define PP (HH * WW)
#define NF 13776
#define NV 6890
#define BATCH 2
#define BIGF 1000000000.0f
#define EPSF 1e-8f
#define TILE 16
#define NSEG 16
#define SEGLEN ((NF + NSEG - 1) / NSEG)
#define CULL 128
#define NWARPS 4

// Precomputed per-(batch,face) data (SoA, device scratch — no allocs)
__device__ float4 g_fa[BATCH * NF];       // A0*inv, B0*inv, A1*inv, B1*inv
__device__ float4 g_fb[BATCH * NF];       // x2, y2, z0, z1
__device__ float2 g_fc[BATCH * NF];       // z2, face_index (int bits)
__device__ float4 g_bb[BATCH * NF];       // xmin, xmax, ymin, ymax
__device__ float2 g_dd[BATCH * NF];       // depth gradient (beta, gamma)
__device__ float2 g_sf[BATCH * NF * 3];   // src flow per corner
__device__ unsigned long long g_zb[BATCH * PP];

__device__ __forceinline__ unsigned int f2sortable(float d) {
    unsigned int u = __float_as_uint(d);
    return u ^ (((unsigned int)((int)u >> 31)) | 0x80000000u);
}
__device__ __forceinline__ float sortable2f(unsigned int s) {
    unsigned int u = (s & 0x80000000u) ? (s ^ 0x80000000u) : ~s;
    return __uint_as_float(u);
}

__global__ void setup_kernel(const float* __restrict__ src_cam,
                             const float* __restrict__ src_verts,
                             const float* __restrict__ tgt_cam,
                             const float* __restrict__ tgt_verts,
                             const int*   __restrict__ faces)
{
    int idx = blockIdx.x * blockDim.x + threadIdx.x;
    if (idx >= BATCH * NF) return;
    int b = idx / NF;
    int f = idx - b * NF;

    int i0 = faces[f * 3 + 0];
    int i1 = faces[f * 3 + 1];
    int i2 = faces[f * 3 + 2];

    float tc0 = tgt_cam[b * 3 + 0];
    float tc1 = tgt_cam[b * 3 + 1];
    float tc2 = tgt_cam[b * 3 + 2];
    const float* tv = tgt_verts + (size_t)b * NV * 3;

    float x0 = tc0 * (tv[i0 * 3 + 0] + tc1);
    float y0 = -(tc0 * (tv[i0 * 3 + 1] + tc2));
    float z0 = tv[i0 * 3 + 2];
    float x1 = tc0 * (tv[i1 * 3 + 0] + tc1);
    float y1 = -(tc0 * (tv[i1 * 3 + 1] + tc2));
    float z1 = tv[i1 * 3 + 2];
    float x2 = tc0 * (tv[i2 * 3 + 0] + tc1);
    float y2 = -(tc0 * (tv[i2 * 3 + 1] + tc2));
    float z2 = tv[i2 * 3 + 2];

    float denom = (y1 - y2) * (x0 - x2) + (x2 - x1) * (y0 - y2);
    bool valid = fabsf(denom) >= EPSF;
    float inv = 1.0f / (valid ? denom : 1.0f);

    float ax = (y1 - y2) * inv, ay = (x2 - x1) * inv;
    float az = (y2 - y0) * inv, aw = (x0 - x2) * inv;
    g_fa[idx] = make_float4(ax, ay, az, aw);
    g_fb[idx] = make_float4(x2, y2, z0, z1);
    g_fc[idx] = make_float2(z2, __int_as_float(f));
    // depth gradient: d(x,y) = w0 z0 + w1 z1 + w2 z2, w affine
    float beta  = ax * z0 + az * z1 - (ax + az) * z2;
    float gamma = ay * z0 + aw * z1 - (ay + aw) * z2;
    g_dd[idx] = make_float2(beta, gamma);

    const float pad = 2.0f / 256.0f;
    float xmn = fminf(x0, fminf(x1, x2)) - pad;
    float xmx = fmaxf(x0, fmaxf(x1, x2)) + pad;
    float ymn = fminf(y0, fminf(y1, y2)) - pad;
    float ymx = fmaxf(y0, fmaxf(y1, y2)) + pad;
    if (!valid) { xmn = 1e30f; xmx = -1e30f; ymn = 1e30f; ymx = -1e30f; }
    g_bb[idx] = make_float4(xmn, xmx, ymn, ymx);

    float sc0 = src_cam[b * 3 + 0];
    float sc1 = src_cam[b * 3 + 1];
    float sc2 = src_cam[b * 3 + 2];
    const float* sv = src_verts + (size_t)b * NV * 3;
    g_sf[idx * 3 + 0] = make_float2(sc0 * (sv[i0 * 3 + 0] + sc1), sc0 * (sv[i0 * 3 + 1] + sc2));
    g_sf[idx * 3 + 1] = make_float2(sc0 * (sv[i1 * 3 + 0] + sc1), sc0 * (sv[i1 * 3 + 1] + sc2));
    g_sf[idx * 3 + 2] = make_float2(sc0 * (sv[i2 * 3 + 0] + sc1), sc0 * (sv[i2 * 3 + 1] + sc2));
}

__global__ void zinit_kernel()
{
    int i = blockIdx.x * blockDim.x + threadIdx.x;
    if (i >= BATCH * PP) return;
    g_zb[i] = ((unsigned long long)f2sortable(BIGF) << 32) | 0xFFFFFFFFull;
}

__global__ __launch_bounds__(CULL) void raster_kernel()
{
    __shared__ float4 s_fa[CULL];
    __shared__ float4 s_fb[CULL];
    __shared__ float2 s_fc[CULL];
    __shared__ float4 s_dd[CULL];          // (dc_tile, beta, gamma, unused)
    __shared__ int    s_wcnt[NWARPS];
    __shared__ float2 s_sub[NWARPS][CULL]; // (dmin_subtile, idx as int bits)

    const int b     = blockIdx.z;
    const int seg   = blockIdx.y;
    const int tileX = blockIdx.x & 15;
    const int tileY = blockIdx.x >> 4;
    const int tid   = threadIdx.x;
    const int lane  = tid & 31;
    const int warp  = tid >> 5;

    // each warp owns an 8x8 subtile
    const int sbx = (warp & 1) * 8;
    const int sby = (warp >> 1) * 8;
    const int p0  = lane * 2;
    const int px0_i = tileX * TILE + sbx + (p0 & 7);
    const int py_i  = tileY * TILE + sby + (p0 >> 3);
    const float px0 = ((float)px0_i + 0.5f) / 256.0f * 2.0f - 1.0f;
    const float px1 = ((float)(px0_i + 1) + 0.5f) / 256.0f * 2.0f - 1.0f;
    const float py  = ((float)py_i + 0.5f) / 256.0f * 2.0f - 1.0f;

    // tile pixel-center rectangle (16x16)
    const float tx0 = ((float)(tileX * TILE)            + 0.5f) / 256.0f * 2.0f - 1.0f;
    const float tx1 = ((float)(tileX * TILE + TILE - 1) + 0.5f) / 256.0f * 2.0f - 1.0f;
    const float ty0 = ((float)(tileY * TILE)            + 0.5f) / 256.0f * 2.0f - 1.0f;
    const float ty1 = ((float)(tileY * TILE + TILE - 1) + 0.5f) / 256.0f * 2.0f - 1.0f;
    const float cx  = 0.5f * (tx0 + tx1);
    const float cy  = 0.5f * (ty0 + ty1);
    const float hx  = 0.5f * (tx1 - tx0);
    const float hy  = 0.5f * (ty1 - ty0);

    // subtile pixel-center rect (8x8)
    const float scx = ((float)(tileX * TILE + sbx) + 4.0f) / 128.0f - 1.0f;
    const float scy = ((float)(tileY * TILE + sby) + 4.0f) / 128.0f - 1.0f;
    const float shx = 3.5f / 128.0f;
    const float shy = 3.5f / 128.0f;
    const float dxs = scx - cx;
    const float dys = scy - cy;

    const float4* __restrict__ fa = g_fa + b * NF;
    const float4* __restrict__ fb = g_fb + b * NF;
    const float2* __restrict__ fc = g_fc + b * NF;
    const float4* __restrict__ bb = g_bb + b * NF;
    const float2* __restrict__ dd = g_dd + b * NF;

    unsigned long long* zb = g_zb + (size_t)b * PP;
    // this thread's pixel-pair slot in the global z-buffer (16B aligned: px0_i even)
    const unsigned long long* zpair = zb + py_i * WW + px0_i;

    float zmin0 = BIGF, zmin1 = BIGF;
    int   best0 = -1,   best1 = -1;
    float gz0 = BIGF, gz1 = BIGF;  // global snapshot depths (only ever decrease)
    float zmaxw = BIGF;            // warp bound: max_p min(local zmin_p, snapshot_p)

    const int fbeg = seg * SEGLEN;
    const int fend = min(fbeg + SEGLEN, NF);

    for (int base = fbeg; base < fend; base += CULL) {
        // ---- refresh global z snapshot (racy but monotone => conservative) ----
        {
            ulonglong2 gk = *(const ulonglong2*)zpair;
            gz0 = fminf(gz0, sortable2f((unsigned int)(gk.x >> 32)));
            gz1 = fminf(gz1, sortable2f((unsigned int)(gk.y >> 32)));
            float zm = fmaxf(fminf(zmin0, gz0), fminf(zmin1, gz1));
            #pragma unroll
            for (int d = 16; d >= 1; d >>= 1)
                zm = fmaxf(zm, __shfl_xor_sync(0xffffffffu, zm, d));
            zmaxw = zm;
        }

        // ---- level 1: tile cull (coalesced, 1 face/thread) ----
        int f = base + tid;
        bool pass = false;
        float dc = 0.0f, beta = 0.0f, gamma = 0.0f;
        if (f < fend) {
            float4 bx = bb[f];
            pass = (bx.x <= tx1) & (bx.y >= tx0) & (bx.z <= ty1) & (bx.w >= ty0);
            if (pass) {
                float4 a  = fa[f];
                float4 c4 = fb[f];
                float z2  = fc[f].x;
                float dxc = cx - c4.x;
                float dyc = cy - c4.y;
                float w0c = a.x * dxc + a.y * dyc;
                float w1c = a.z * dxc + a.w * dyc;
                float w2c = 1.0f - w0c - w1c;
                float s0  = fabsf(a.x) * hx + fabsf(a.y) * hy;
                float s1  = fabsf(a.z) * hx + fabsf(a.w) * hy;
                float s2  = fabsf(a.x + a.z) * hx + fabsf(a.y + a.w) * hy;
                float m0  = 1e-5f * (fabsf(w0c) + s0) + 1e-6f;
                float m1  = 1e-5f * (fabsf(w1c) + s1) + 1e-6f;
                float m2  = 1e-5f * (fabsf(w2c) + s2) + 1e-6f;
                pass = (w0c + s0 >= -m0) & (w1c + s1 >= -m1) & (w2c + s2 >= -m2);
                if (pass) {
                    dc = w0c * c4.z + w1c * c4.w + w2c * z2;  // depth at tile center
                    float2 g = dd[f];
                    beta = g.x; gamma = g.y;
                }
            }
        }
        unsigned m = __ballot_sync(0xffffffffu, pass);
        if (lane == 0) s_wcnt[warp] = __popc(m);
        __syncthreads();

        int off = 0;
        int cnt = 0;
        #pragma unroll
        for (int w = 0; w < NWARPS; w++) {
            int c = s_wcnt[w];
            if (w < warp) off += c;
            cnt += c;
        }
        off += __popc(m & ((1u << lane) - 1u));
        if (pass) {
            s_fa[off] = fa[f];
            s_fb[off] = fb[f];
            s_fc[off] = fc[f];
            s_dd[off] = make_float4(dc, beta, gamma, 0.0f);
        }
        __syncthreads();

        // ---- level 2: per-warp 8x8 subtile cull + conservative min-depth ----
        int scnt = 0;
        for (int j0 = 0; j0 < cnt; j0 += 32) {
            int j = j0 + lane;
            bool sp = false;
            float dmins = 0.0f;
            if (j < cnt) {
                float4 a  = s_fa[j];
                float2 xy = make_float2(s_fb[j].x, s_fb[j].y);
                float dxc = scx - xy.x;
                float dyc = scy - xy.y;
                float w0c = a.x * dxc + a.y * dyc;
                float w1c = a.z * dxc + a.w * dyc;
                float w2c = 1.0f - w0c - w1c;
                float s0  = fabsf(a.x) * shx + fabsf(a.y) * shy;
                float s1  = fabsf(a.z) * shx + fabsf(a.w) * shy;
                float s2  = fabsf(a.x + a.z) * shx + fabsf(a.y + a.w) * shy;
                float m0  = 1e-5f * (fabsf(w0c) + s0) + 1e-6f;
                float m1  = 1e-5f * (fabsf(w1c) + s1) + 1e-6f;
                float m2  = 1e-5f * (fabsf(w2c) + s2) + 1e-6f;
                sp = (w0c + s0 >= -m0) & (w1c + s1 >= -m1) & (w2c + s2 >= -m2);
                if (sp) {
                    float4 dv = s_dd[j];
                    float sd  = fabsf(dv.y) * shx + fabsf(dv.z) * shy;
                    float dcs = dv.x + dv.y * dxs + dv.z * dys;   // depth at subtile center
                    float mg  = 1e-4f * (fabsf(dcs) + sd) + 1e-5f;
                    dmins = dcs - sd - mg;
                    // early-z: faces provably behind every achieved depth can't win
                    sp = dmins <= zmaxw;
                }
            }
            unsigned sm = __ballot_sync(0xffffffffu, sp);
            if (sp) s_sub[warp][scnt + __popc(sm & ((1u << lane) - 1u))] =
                        make_float2(dmins, __int_as_float(j));
            scnt += __popc(sm);
        }

        // ---- sweep: this warp's subtile list, 2px/lane, early-z skip ----
        for (int k = 0; k < scnt; k++) {
            if ((k & 15) == 0) {
                float zm = fmaxf(fminf(zmin0, gz0), fminf(zmin1, gz1));
                #pragma unroll
                for (int d = 16; d >= 1; d >>= 1)
                    zm = fmaxf(zm, __shfl_xor_sync(0xffffffffu, zm, d));
                zmaxw = zm;
            }
            float2 di = s_sub[warp][k];
            if (di.x > zmaxw) continue;          // uniform skip: face behind all pixels
            int idx   = __float_as_int(di.y);
            float4 a  = s_fa[idx];
            float4 c4 = s_fb[idx];
            float2 e  = s_fc[idx];
            float dy  = py  - c4.y;
            float dx0 = px0 - c4.x;
            float dx1 = px1 - c4.x;
            float t0  = a.y * dy;
            float t1  = a.w * dy;
            float w0a = fmaf(a.x, dx0, t0);
            float w0b = fmaf(a.x, dx1, t0);
            float w1a = fmaf(a.z, dx0, t1);
            float w1b = fmaf(a.z, dx1, t1);
            float w2a = 1.0f - w0a - w1a;
            float w2b = 1.0f - w0b - w1b;
            float da  = fmaf(w0a, c4.z, fmaf(w1a, c4.w, w2a * e.x));
            float db  = fmaf(w0b, c4.z, fmaf(w1b, c4.w, w2b * e.x));
            int oa = __float_as_int(w0a) | __float_as_int(w1a) | __float_as_int(w2a);
            int ob = __float_as_int(w0b) | __float_as_int(w1b) | __float_as_int(w2b);
            if ((oa >= 0) && (da < zmin0)) { zmin0 = da; best0 = __float_as_int(e.y); }
            if ((ob >= 0) && (db < zmin1)) { zmin1 = db; best1 = __float_as_int(e.y); }
        }
        __syncthreads();
    }

    if (best0 >= 0) {
        unsigned long long key =
            ((unsigned long long)f2sortable(zmin0) << 32) | (unsigned int)best0;
        atomicMin(&zb[py_i * WW + px0_i], key);
    }
    if (best1 >= 0) {
        unsigned long long key =
            ((unsigned long long)f2sortable(zmin1) << 32) | (unsigned int)best1;
        atomicMin(&zb[py_i * WW + px0_i + 1], key);
    }
}

__global__ __launch_bounds__(256) void resolve_kernel(const float* __restrict__ src_img,
                                                      float* __restrict__ out)
{
    const int b   = blockIdx.y;
    const int pix = blockIdx.x * 256 + threadIdx.x;
    const int px_i = pix & (WW - 1);
    const int py_i = pix >> 8;
    const float px = ((float)px_i + 0.5f) / 256.0f * 2.0f - 1.0f;
    const float py = ((float)py_i + 0.5f) / 256.0f * 2.0f - 1.0f;

    unsigned long long key = g_zb[(size_t)b * PP + pix];
    unsigned int face = (unsigned int)(key & 0xFFFFFFFFull);

    float fx, fy;
    if (face != 0xFFFFFFFFu) {
        int gi = b * NF + (int)face;
        float4 a  = g_fa[gi];
        float4 c4 = g_fb[gi];
        float dx = px - c4.x;
        float dy = py - c4.y;
        float w0 = fmaf(a.x, dx, a.y * dy);
        float w1 = fmaf(a.z, dx, a.w * dy);
        float w2 = 1.0f - w0 - w1;
        float2 s0 = g_sf[gi * 3 + 0];
        float2 s1 = g_sf[gi * 3 + 1];
        float2 s2 = g_sf[gi * 3 + 2];
        fx = w0 * s0.x + w1 * s1.x + w2 * s2.x;
        fy = w0 * s0.y + w1 * s1.y + w2 * s2.y;
    } else {
        fx = -2.0f;
        fy = -2.0f;
    }

    float ix = fminf(fmaxf(((fx + 1.0f) * 256.0f - 1.0f) * 0.5f, 0.0f), 255.0f);
    float iy = fminf(fmaxf(((fy + 1.0f) * 256.0f - 1.0f) * 0.5f, 0.0f), 255.0f);
    float x0f = floorf(ix);
    float y0f = floorf(iy);
    float wx = ix - x0f;
    float wy = iy - y0f;
    int x0i = (int)x0f;
    int y0i = (int)y0f;
    int x1i = min(x0i + 1, WW - 1);
    int y1i = min(y0i + 1, HH - 1);

    float wa = (1.0f - wx) * (1.0f - wy);
    float wb = wx * (1.0f - wy);
    float wc = (1.0f - wx) * wy;
    float wd = wx * wy;

    const float* img = src_img + (size_t)b * 3 * HH * WW;
    #pragma unroll
    for (int c = 0; c < 3; c++) {
        const float* p = img + (size_t)c * HH * WW;
        float Ia = p[y0i * WW + x0i];
        float Ib = p[y0i * WW + x1i];
        float Ic = p[y1i * WW + x0i];
        float Id = p[y1i * WW + x1i];
        out[(((size_t)b * 3 + c) * HH + py_i) * WW + px_i] =
            Ia * wa + Ib * wb + Ic * wc + Id * wd;
    }
}

extern "C" void kernel_launch(void* const* d_in, const int* in_sizes, int n_in,
                              void* d_out, int out_size)
{
    const float* src_img   = (const float*)d_in[0];
    const float* src_cam   = (const float*)d_in[1];
    const float* src_verts = (const float*)d_in[2];
    const float* tgt_cam   = (const float*)d_in[3];
    const float* tgt_verts = (const float*)d_in[4];
    const int*   faces     = (const int*)d_in[5];
    float* out = (float*)d_out;

    int n = BATCH * NF;
    setup_kernel<<<(n + 255) / 256, 256>>>(src_cam, src_verts, tgt_cam, tgt_verts, faces);
    zinit_kernel<<<(BATCH * PP + 255) / 256, 256>>>();
    dim3 rgrid(256, NSEG, BATCH);
    raster_kernel<<<rgrid, CULL>>>();
    dim3 ggrid(PP / 256, BATCH);
    resolve_kernel<<<ggrid, 256>>>(src_img, out);
}

// round 11
// speedup vs baseline: 1.0637x; 1.0637x over previous
#include <cuda_runtime.h>

#define HH 256
#define WW 256
#define PP (HH * WW)
#define NF 13776
#define NV 6890
#define BATCH 2
#define BIGF 1000000000.0f
#define EPSF 1e-8f
#define TILE 16
#define NSEG 16
#define SEGLEN ((NF + NSEG - 1) / NSEG)
#define CULL 128
#define NWARPS 4
#define NBIN 1024

// Original per-(batch,face) data (indexed by face id; used by resolve)
__device__ float4 g_fa[BATCH * NF];
__device__ float4 g_fb[BATCH * NF];
__device__ float2 g_sf[BATCH * NF * 3];
// Sort scratch
__device__ float2 g_fc[BATCH * NF];       // z2, face id (int bits)
__device__ float4 g_bb[BATCH * NF];
__device__ float2 g_dd[BATCH * NF];       // depth gradient
__device__ int    g_bin[BATCH * NF];
__device__ int    g_hist[BATCH * NBIN];
__device__ int    g_pos[BATCH * NBIN];
// Depth-sorted copies (raster reads these sequentially)
__device__ float4 g_fa_s[BATCH * NF];
__device__ float4 g_fb_s[BATCH * NF];
__device__ float2 g_fc_s[BATCH * NF];
__device__ float4 g_bb_s[BATCH * NF];
__device__ float2 g_dd_s[BATCH * NF];
__device__ float  g_zfl[BATCH * NF];      // monotone bin-floor depth at sorted pos
__device__ unsigned long long g_zb[BATCH * PP];

__device__ __forceinline__ unsigned int f2sortable(float d) {
    unsigned int u = __float_as_uint(d);
    return u ^ (((unsigned int)((int)u >> 31)) | 0x80000000u);
}
__device__ __forceinline__ float sortable2f(unsigned int s) {
    unsigned int u = (s & 0x80000000u) ? (s ^ 0x80000000u) : ~s;
    return __uint_as_float(u);
}

__global__ void setup_kernel(const float* __restrict__ src_cam,
                             const float* __restrict__ src_verts,
                             const float* __restrict__ tgt_cam,
                             const float* __restrict__ tgt_verts,
                             const int*   __restrict__ faces)
{
    int idx = blockIdx.x * blockDim.x + threadIdx.x;
    if (idx >= BATCH * NF) return;
    int b = idx / NF;
    int f = idx - b * NF;

    int i0 = faces[f * 3 + 0];
    int i1 = faces[f * 3 + 1];
    int i2 = faces[f * 3 + 2];

    float tc0 = tgt_cam[b * 3 + 0];
    float tc1 = tgt_cam[b * 3 + 1];
    float tc2 = tgt_cam[b * 3 + 2];
    const float* tv = tgt_verts + (size_t)b * NV * 3;

    float x0 = tc0 * (tv[i0 * 3 + 0] + tc1);
    float y0 = -(tc0 * (tv[i0 * 3 + 1] + tc2));
    float z0 = tv[i0 * 3 + 2];
    float x1 = tc0 * (tv[i1 * 3 + 0] + tc1);
    float y1 = -(tc0 * (tv[i1 * 3 + 1] + tc2));
    float z1 = tv[i1 * 3 + 2];
    float x2 = tc0 * (tv[i2 * 3 + 0] + tc1);
    float y2 = -(tc0 * (tv[i2 * 3 + 1] + tc2));
    float z2 = tv[i2 * 3 + 2];

    float denom = (y1 - y2) * (x0 - x2) + (x2 - x1) * (y0 - y2);
    bool valid = fabsf(denom) >= EPSF;
    float inv = 1.0f / (valid ? denom : 1.0f);

    float ax = (y1 - y2) * inv, ay = (x2 - x1) * inv;
    float az = (y2 - y0) * inv, aw = (x0 - x2) * inv;
    g_fa[idx] = make_float4(ax, ay, az, aw);
    g_fb[idx] = make_float4(x2, y2, z0, z1);
    g_fc[idx] = make_float2(z2, __int_as_float(f));
    float beta  = ax * z0 + az * z1 - (ax + az) * z2;
    float gamma = ay * z0 + aw * z1 - (ay + aw) * z2;
    g_dd[idx] = make_float2(beta, gamma);

    const float pad = 2.0f / 256.0f;
    float xmn = fminf(x0, fminf(x1, x2)) - pad;
    float xmx = fmaxf(x0, fmaxf(x1, x2)) + pad;
    float ymn = fminf(y0, fminf(y1, y2)) - pad;
    float ymx = fmaxf(y0, fmaxf(y1, y2)) + pad;
    if (!valid) { xmn = 1e30f; xmx = -1e30f; ymn = 1e30f; ymx = -1e30f; }
    g_bb[idx] = make_float4(xmn, xmx, ymn, ymx);

    // conservative min-depth sort key -> bin
    float zs = fminf(z0, fminf(z1, z2));
    float safe = zs - (1e-5f * fabsf(zs) + 1e-6f);
    int bin = valid ? min(max((int)floorf((safe + 8.0f) * 64.0f), 0), NBIN - 1)
                    : NBIN - 1;
    g_bin[idx] = bin;

    float sc0 = src_cam[b * 3 + 0];
    float sc1 = src_cam[b * 3 + 1];
    float sc2 = src_cam[b * 3 + 2];
    const float* sv = src_verts + (size_t)b * NV * 3;
    g_sf[idx * 3 + 0] = make_float2(sc0 * (sv[i0 * 3 + 0] + sc1), sc0 * (sv[i0 * 3 + 1] + sc2));
    g_sf[idx * 3 + 1] = make_float2(sc0 * (sv[i1 * 3 + 0] + sc1), sc0 * (sv[i1 * 3 + 1] + sc2));
    g_sf[idx * 3 + 2] = make_float2(sc0 * (sv[i2 * 3 + 0] + sc1), sc0 * (sv[i2 * 3 + 1] + sc2));
}

__global__ void zinit_kernel()
{
    int i = blockIdx.x * blockDim.x + threadIdx.x;
    if (i < BATCH * PP)
        g_zb[i] = ((unsigned long long)f2sortable(BIGF) << 32) | 0xFFFFFFFFull;
    if (i < BATCH * NBIN)
        g_hist[i] = 0;
}

__global__ void hist_kernel()
{
    int idx = blockIdx.x * blockDim.x + threadIdx.x;
    if (idx >= BATCH * NF) return;
    int b = idx / NF;
    atomicAdd(&g_hist[b * NBIN + g_bin[idx]], 1);
}

__global__ __launch_bounds__(NBIN) void scan_kernel()
{
    __shared__ int sh[NBIN];
    int b = blockIdx.x;
    int t = threadIdx.x;
    int v0 = g_hist[b * NBIN + t];
    sh[t] = v0;
    for (int d = 1; d < NBIN; d <<= 1) {
        __syncthreads();
        int v = (t >= d) ? sh[t - d] : 0;
        __syncthreads();
        sh[t] += v;
    }
    __syncthreads();
    g_pos[b * NBIN + t] = sh[t] - v0;   // exclusive
}

__global__ void scatter_kernel()
{
    int idx = blockIdx.x * blockDim.x + threadIdx.x;
    if (idx >= BATCH * NF) return;
    int b = idx / NF;
    int bin = g_bin[idx];
    int pos = atomicAdd(&g_pos[b * NBIN + bin], 1);
    int dst = b * NF + pos;
    g_fa_s[dst] = g_fa[idx];
    g_fb_s[dst] = g_fb[idx];
    g_fc_s[dst] = g_fc[idx];
    g_bb_s[dst] = g_bb[idx];
    g_dd_s[dst] = g_dd[idx];
    g_zfl[dst] = (bin == 0) ? -BIGF : ((float)bin * (1.0f / 64.0f) - 8.0f);
}

__global__ __launch_bounds__(CULL) void raster_kernel()
{
    __shared__ float4 s_fa[CULL];
    __shared__ float4 s_fb[CULL];
    __shared__ float2 s_fc[CULL];
    __shared__ float4 s_dd[CULL];
    __shared__ int    s_wcnt[NWARPS];
    __shared__ float  s_zw[NWARPS];
    __shared__ float2 s_sub[NWARPS][CULL];

    const int b     = blockIdx.z;
    const int seg   = blockIdx.y;
    const int tileX = blockIdx.x & 15;
    const int tileY = blockIdx.x >> 4;
    const int tid   = threadIdx.x;
    const int lane  = tid & 31;
    const int warp  = tid >> 5;

    const int sbx = (warp & 1) * 8;
    const int sby = (warp >> 1) * 8;
    const int p0  = lane * 2;
    const int px0_i = tileX * TILE + sbx + (p0 & 7);
    const int py_i  = tileY * TILE + sby + (p0 >> 3);
    const float px0 = ((float)px0_i + 0.5f) / 256.0f * 2.0f - 1.0f;
    const float px1 = ((float)(px0_i + 1) + 0.5f) / 256.0f * 2.0f - 1.0f;
    const float py  = ((float)py_i + 0.5f) / 256.0f * 2.0f - 1.0f;

    const float tx0 = ((float)(tileX * TILE)            + 0.5f) / 256.0f * 2.0f - 1.0f;
    const float tx1 = ((float)(tileX * TILE + TILE - 1) + 0.5f) / 256.0f * 2.0f - 1.0f;
    const float ty0 = ((float)(tileY * TILE)            + 0.5f) / 256.0f * 2.0f - 1.0f;
    const float ty1 = ((float)(tileY * TILE + TILE - 1) + 0.5f) / 256.0f * 2.0f - 1.0f;
    const float cx  = 0.5f * (tx0 + tx1);
    const float cy  = 0.5f * (ty0 + ty1);
    const float hx  = 0.5f * (tx1 - tx0);
    const float hy  = 0.5f * (ty1 - ty0);

    const float scx = ((float)(tileX * TILE + sbx) + 4.0f) / 128.0f - 1.0f;
    const float scy = ((float)(tileY * TILE + sby) + 4.0f) / 128.0f - 1.0f;
    const float shx = 3.5f / 128.0f;
    const float shy = 3.5f / 128.0f;
    const float dxs = scx - cx;
    const float dys = scy - cy;

    const float4* __restrict__ fa = g_fa_s + b * NF;
    const float4* __restrict__ fb = g_fb_s + b * NF;
    const float2* __restrict__ fc = g_fc_s + b * NF;
    const float4* __restrict__ bb = g_bb_s + b * NF;
    const float2* __restrict__ dd = g_dd_s + b * NF;
    const float*  __restrict__ zfl = g_zfl + b * NF;

    unsigned long long* zb = g_zb + (size_t)b * PP;
    unsigned long long* zslot0 = zb + py_i * WW + px0_i;
    const unsigned long long* zpair = zslot0;

    float zmin0 = BIGF, zmin1 = BIGF;
    int   best0 = -1,   best1 = -1;
    float wz0 = BIGF, wz1 = BIGF;   // last published depths
    float gz0 = BIGF, gz1 = BIGF;   // snapshot depths (monotone non-increasing)
    float zmaxw = BIGF;

    const int fbeg = seg * SEGLEN;
    const int fend = min(fbeg + SEGLEN, NF);

    for (int base = fbeg; base < fend; base += CULL) {
        // refresh snapshot + warp bound; CTA bound for monotone break
        {
            ulonglong2 gk = *(const ulonglong2*)zpair;
            gz0 = fminf(gz0, sortable2f((unsigned int)(gk.x >> 32)));
            gz1 = fminf(gz1, sortable2f((unsigned int)(gk.y >> 32)));
            float zm = fmaxf(fminf(zmin0, gz0), fminf(zmin1, gz1));
            #pragma unroll
            for (int d = 16; d >= 1; d >>= 1)
                zm = fmaxf(zm, __shfl_xor_sync(0xffffffffu, zm, d));
            zmaxw = zm;
            if (lane == 0) s_zw[warp] = zm;
        }
        __syncthreads();
        float zmaxc = fmaxf(fmaxf(s_zw[0], s_zw[1]), fmaxf(s_zw[2], s_zw[3]));
        // monotone break: every remaining face is behind every pixel's achieved z
        if (zfl[base] > zmaxc) break;

        // ---- level 1: tile cull (coalesced) ----
        int f = base + tid;
        bool pass = false;
        float dc = 0.0f, beta = 0.0f, gamma = 0.0f;
        if (f < fend) {
            float4 bx = bb[f];
            pass = (bx.x <= tx1) & (bx.y >= tx0) & (bx.z <= ty1) & (bx.w >= ty0);
            if (pass) {
                float4 a  = fa[f];
                float4 c4 = fb[f];
                float z2  = fc[f].x;
                float dxc = cx - c4.x;
                float dyc = cy - c4.y;
                float w0c = a.x * dxc + a.y * dyc;
                float w1c = a.z * dxc + a.w * dyc;
                float w2c = 1.0f - w0c - w1c;
                float s0  = fabsf(a.x) * hx + fabsf(a.y) * hy;
                float s1  = fabsf(a.z) * hx + fabsf(a.w) * hy;
                float s2  = fabsf(a.x + a.z) * hx + fabsf(a.y + a.w) * hy;
                float m0  = 1e-5f * (fabsf(w0c) + s0) + 1e-6f;
                float m1  = 1e-5f * (fabsf(w1c) + s1) + 1e-6f;
                float m2  = 1e-5f * (fabsf(w2c) + s2) + 1e-6f;
                pass = (w0c + s0 >= -m0) & (w1c + s1 >= -m1) & (w2c + s2 >= -m2);
                if (pass) {
                    dc = w0c * c4.z + w1c * c4.w + w2c * z2;
                    float2 g = dd[f];
                    beta = g.x; gamma = g.y;
                }
            }
        }
        unsigned m = __ballot_sync(0xffffffffu, pass);
        if (lane == 0) s_wcnt[warp] = __popc(m);
        __syncthreads();

        int off = 0;
        int cnt = 0;
        #pragma unroll
        for (int w = 0; w < NWARPS; w++) {
            int c = s_wcnt[w];
            if (w < warp) off += c;
            cnt += c;
        }
        off += __popc(m & ((1u << lane) - 1u));
        if (pass) {
            s_fa[off] = fa[f];
            s_fb[off] = fb[f];
            s_fc[off] = fc[f];
            s_dd[off] = make_float4(dc, beta, gamma, 0.0f);
        }
        __syncthreads();

        // ---- level 2: per-warp subtile cull + conservative min-depth ----
        int scnt = 0;
        for (int j0 = 0; j0 < cnt; j0 += 32) {
            int j = j0 + lane;
            bool sp = false;
            float dmins = 0.0f;
            if (j < cnt) {
                float4 a  = s_fa[j];
                float2 xy = make_float2(s_fb[j].x, s_fb[j].y);
                float dxc = scx - xy.x;
                float dyc = scy - xy.y;
                float w0c = a.x * dxc + a.y * dyc;
                float w1c = a.z * dxc + a.w * dyc;
                float w2c = 1.0f - w0c - w1c;
                float s0  = fabsf(a.x) * shx + fabsf(a.y) * shy;
                float s1  = fabsf(a.z) * shx + fabsf(a.w) * shy;
                float s2  = fabsf(a.x + a.z) * shx + fabsf(a.y + a.w) * shy;
                float m0  = 1e-5f * (fabsf(w0c) + s0) + 1e-6f;
                float m1  = 1e-5f * (fabsf(w1c) + s1) + 1e-6f;
                float m2  = 1e-5f * (fabsf(w2c) + s2) + 1e-6f;
                sp = (w0c + s0 >= -m0) & (w1c + s1 >= -m1) & (w2c + s2 >= -m2);
                if (sp) {
                    float4 dv = s_dd[j];
                    float sd  = fabsf(dv.y) * shx + fabsf(dv.z) * shy;
                    float dcs = dv.x + dv.y * dxs + dv.z * dys;
                    float mg  = 1e-4f * (fabsf(dcs) + sd) + 1e-5f;
                    dmins = dcs - sd - mg;
                    sp = dmins <= zmaxw;
                }
            }
            unsigned sm = __ballot_sync(0xffffffffu, sp);
            if (sp) s_sub[warp][scnt + __popc(sm & ((1u << lane) - 1u))] =
                        make_float2(dmins, __int_as_float(j));
            scnt += __popc(sm);
        }

        // ---- sweep ----
        for (int k = 0; k < scnt; k++) {
            if ((k & 15) == 0) {
                float zm = fmaxf(fminf(zmin0, gz0), fminf(zmin1, gz1));
                #pragma unroll
                for (int d = 16; d >= 1; d >>= 1)
                    zm = fmaxf(zm, __shfl_xor_sync(0xffffffffu, zm, d));
                zmaxw = zm;
            }
            float2 di = s_sub[warp][k];
            if (di.x > zmaxw) continue;
            int idx   = __float_as_int(di.y);
            float4 a  = s_fa[idx];
            float4 c4 = s_fb[idx];
            float2 e  = s_fc[idx];
            float dy  = py  - c4.y;
            float dx0 = px0 - c4.x;
            float dx1 = px1 - c4.x;
            float t0  = a.y * dy;
            float t1  = a.w * dy;
            float w0a = fmaf(a.x, dx0, t0);
            float w0b = fmaf(a.x, dx1, t0);
            float w1a = fmaf(a.z, dx0, t1);
            float w1b = fmaf(a.z, dx1, t1);
            float w2a = 1.0f - w0a - w1a;
            float w2b = 1.0f - w0b - w1b;
            float da  = fmaf(w0a, c4.z, fmaf(w1a, c4.w, w2a * e.x));
            float db  = fmaf(w0b, c4.z, fmaf(w1b, c4.w, w2b * e.x));
            int oa = __float_as_int(w0a) | __float_as_int(w1a) | __float_as_int(w2a);
            int ob = __float_as_int(w0b) | __float_as_int(w1b) | __float_as_int(w2b);
            if ((oa >= 0) && (da < zmin0)) { zmin0 = da; best0 = __float_as_int(e.y); }
            if ((ob >= 0) && (db < zmin1)) { zmin1 = db; best1 = __float_as_int(e.y); }
        }

        // ---- eager publication: make progress visible to other CTAs ----
        if (zmin0 < wz0) {
            wz0 = zmin0;
            unsigned long long key =
                ((unsigned long long)f2sortable(zmin0) << 32) | (unsigned int)best0;
            atomicMin(zslot0, key);
        }
        if (zmin1 < wz1) {
            wz1 = zmin1;
            unsigned long long key =
                ((unsigned long long)f2sortable(zmin1) << 32) | (unsigned int)best1;
            atomicMin(zslot0 + 1, key);
        }
        __syncthreads();
    }

    if (best0 >= 0 && zmin0 < wz0) {
        unsigned long long key =
            ((unsigned long long)f2sortable(zmin0) << 32) | (unsigned int)best0;
        atomicMin(zslot0, key);
    }
    if (best1 >= 0 && zmin1 < wz1) {
        unsigned long long key =
            ((unsigned long long)f2sortable(zmin1) << 32) | (unsigned int)best1;
        atomicMin(zslot0 + 1, key);
    }
}

__global__ __launch_bounds__(256) void resolve_kernel(const float* __restrict__ src_img,
                                                      float* __restrict__ out)
{
    const int b   = blockIdx.y;
    const int pix = blockIdx.x * 256 + threadIdx.x;
    const int px_i = pix & (WW - 1);
    const int py_i = pix >> 8;
    const float px = ((float)px_i + 0.5f) / 256.0f * 2.0f - 1.0f;
    const float py = ((float)py_i + 0.5f) / 256.0f * 2.0f - 1.0f;

    unsigned long long key = g_zb[(size_t)b * PP + pix];
    unsigned int face = (unsigned int)(key & 0xFFFFFFFFull);

    float fx, fy;
    if (face != 0xFFFFFFFFu) {
        int gi = b * NF + (int)face;
        float4 a  = g_fa[gi];
        float4 c4 = g_fb[gi];
        float dx = px - c4.x;
        float dy = py - c4.y;
        float w0 = fmaf(a.x, dx, a.y * dy);
        float w1 = fmaf(a.z, dx, a.w * dy);
        float w2 = 1.0f - w0 - w1;
        float2 s0 = g_sf[gi * 3 + 0];
        float2 s1 = g_sf[gi * 3 + 1];
        float2 s2 = g_sf[gi * 3 + 2];
        fx = w0 * s0.x + w1 * s1.x + w2 * s2.x;
        fy = w0 * s0.y + w1 * s1.y + w2 * s2.y;
    } else {
        fx = -2.0f;
        fy = -2.0f;
    }

    float ix = fminf(fmaxf(((fx + 1.0f) * 256.0f - 1.0f) * 0.5f, 0.0f), 255.0f);
    float iy = fminf(fmaxf(((fy + 1.0f) * 256.0f - 1.0f) * 0.5f, 0.0f), 255.0f);
    float x0f = floorf(ix);
    float y0f = floorf(iy);
    float wx = ix - x0f;
    float wy = iy - y0f;
    int x0i = (int)x0f;
    int y0i = (int)y0f;
    int x1i = min(x0i + 1, WW - 1);
    int y1i = min(y0i + 1, HH - 1);

    float wa = (1.0f - wx) * (1.0f - wy);
    float wb = wx * (1.0f - wy);
    float wc = (1.0f - wx) * wy;
    float wd = wx * wy;

    const float* img = src_img + (size_t)b * 3 * HH * WW;
    #pragma unroll
    for (int c = 0; c < 3; c++) {
        const float* p = img + (size_t)c * HH * WW;
        float Ia = p[y0i * WW + x0i];
        float Ib = p[y0i * WW + x1i];
        float Ic = p[y1i * WW + x0i];
        float Id = p[y1i * WW + x1i];
        out[(((size_t)b * 3 + c) * HH + py_i) * WW + px_i] =
            Ia * wa + Ib * wb + Ic * wc + Id * wd;
    }
}

extern "C" void kernel_launch(void* const* d_in, const int* in_sizes, int n_in,
                              void* d_out, int out_size)
{
    const float* src_img   = (const float*)d_in[0];
    const float* src_cam   = (const float*)d_in[1];
    const float* src_verts = (const float*)d_in[2];
    const float* tgt_cam   = (const float*)d_in[3];
    const float* tgt_verts = (const float*)d_in[4];
    const int*   faces     = (const int*)d_in[5];
    float* out = (float*)d_out;

    int n = BATCH * NF;
    setup_kernel<<<(n + 255) / 256, 256>>>(src_cam, src_verts, tgt_cam, tgt_verts, faces);
    zinit_kernel<<<(BATCH * PP + 255) / 256, 256>>>();
    hist_kernel<<<(n + 255) / 256, 256>>>();
    scan_kernel<<<BATCH, NBIN>>>();
    scatter_kernel<<<(n + 255) / 256, 256>>>();
    dim3 rgrid(256, NSEG, BATCH);
    raster_kernel<<<rgrid, CULL>>>();
    dim3 ggrid(PP / 256, BATCH);
    resolve_kernel<<<ggrid, 256>>>(src_img, out);
}

// round 12
// speedup vs baseline: 1.0696x; 1.0055x over previous
#include <cuda_runtime.h>

#define HH 256
#define WW 256
#define PP (HH * WW)
#define NF 13776
#define NV 6890
#define BATCH 2
#define BIGF 1000000000.0f
#define EPSF 1e-8f
#define TILE 16
#define NSEG 16
#define SEGLEN ((NF + NSEG - 1) / NSEG)
#define CULL 128
#define NWARPS 4
#define NBIN 1024

// Original per-(batch,face) data (indexed by face id; used by resolve)
__device__ float4 g_fa[BATCH * NF];
__device__ float4 g_fb[BATCH * NF];
__device__ float2 g_sf[BATCH * NF * 3];
// Sort scratch
__device__ float2 g_fc[BATCH * NF];       // z2, face id (int bits)
__device__ float4 g_bb[BATCH * NF];
__device__ float2 g_dd[BATCH * NF];       // depth gradient
__device__ int    g_bin[BATCH * NF];
__device__ int    g_hist[BATCH * NBIN];
__device__ int    g_pos[BATCH * NBIN];
// Depth-sorted copies (raster reads these sequentially)
__device__ float4 g_fa_s[BATCH * NF];
__device__ float4 g_fb_s[BATCH * NF];
__device__ float2 g_fc_s[BATCH * NF];
__device__ float4 g_bb_s[BATCH * NF];
__device__ float2 g_dd_s[BATCH * NF];
__device__ float  g_zfl[BATCH * NF];      // monotone bin-floor depth at sorted pos
__device__ unsigned long long g_zb[BATCH * PP];

__device__ __forceinline__ unsigned int f2sortable(float d) {
    unsigned int u = __float_as_uint(d);
    return u ^ (((unsigned int)((int)u >> 31)) | 0x80000000u);
}
__device__ __forceinline__ float sortable2f(unsigned int s) {
    unsigned int u = (s & 0x80000000u) ? (s ^ 0x80000000u) : ~s;
    return __uint_as_float(u);
}

// zinit FIRST: z-buffer init + hist zero (setup's fused hist needs zeroed bins)
__global__ void zinit_kernel()
{
    int i = blockIdx.x * blockDim.x + threadIdx.x;
    if (i < BATCH * PP)
        g_zb[i] = ((unsigned long long)f2sortable(BIGF) << 32) | 0xFFFFFFFFull;
    if (i < BATCH * NBIN)
        g_hist[i] = 0;
}

__global__ void setup_kernel(const float* __restrict__ src_cam,
                             const float* __restrict__ src_verts,
                             const float* __restrict__ tgt_cam,
                             const float* __restrict__ tgt_verts,
                             const int*   __restrict__ faces)
{
    int idx = blockIdx.x * blockDim.x + threadIdx.x;
    if (idx >= BATCH * NF) return;
    int b = idx / NF;
    int f = idx - b * NF;

    int i0 = faces[f * 3 + 0];
    int i1 = faces[f * 3 + 1];
    int i2 = faces[f * 3 + 2];

    float tc0 = tgt_cam[b * 3 + 0];
    float tc1 = tgt_cam[b * 3 + 1];
    float tc2 = tgt_cam[b * 3 + 2];
    const float* tv = tgt_verts + (size_t)b * NV * 3;

    float x0 = tc0 * (tv[i0 * 3 + 0] + tc1);
    float y0 = -(tc0 * (tv[i0 * 3 + 1] + tc2));
    float z0 = tv[i0 * 3 + 2];
    float x1 = tc0 * (tv[i1 * 3 + 0] + tc1);
    float y1 = -(tc0 * (tv[i1 * 3 + 1] + tc2));
    float z1 = tv[i1 * 3 + 2];
    float x2 = tc0 * (tv[i2 * 3 + 0] + tc1);
    float y2 = -(tc0 * (tv[i2 * 3 + 1] + tc2));
    float z2 = tv[i2 * 3 + 2];

    float denom = (y1 - y2) * (x0 - x2) + (x2 - x1) * (y0 - y2);
    bool valid = fabsf(denom) >= EPSF;
    float inv = 1.0f / (valid ? denom : 1.0f);

    float ax = (y1 - y2) * inv, ay = (x2 - x1) * inv;
    float az = (y2 - y0) * inv, aw = (x0 - x2) * inv;
    g_fa[idx] = make_float4(ax, ay, az, aw);
    g_fb[idx] = make_float4(x2, y2, z0, z1);
    g_fc[idx] = make_float2(z2, __int_as_float(f));
    float beta  = ax * z0 + az * z1 - (ax + az) * z2;
    float gamma = ay * z0 + aw * z1 - (ay + aw) * z2;
    g_dd[idx] = make_float2(beta, gamma);

    const float pad = 2.0f / 256.0f;
    float xmn = fminf(x0, fminf(x1, x2)) - pad;
    float xmx = fmaxf(x0, fmaxf(x1, x2)) + pad;
    float ymn = fminf(y0, fminf(y1, y2)) - pad;
    float ymx = fmaxf(y0, fmaxf(y1, y2)) + pad;
    if (!valid) { xmn = 1e30f; xmx = -1e30f; ymn = 1e30f; ymx = -1e30f; }
    g_bb[idx] = make_float4(xmn, xmx, ymn, ymx);

    // conservative min-depth sort key -> bin (+ fused histogram)
    float zs = fminf(z0, fminf(z1, z2));
    float safe = zs - (1e-5f * fabsf(zs) + 1e-6f);
    int bin = valid ? min(max((int)floorf((safe + 8.0f) * 64.0f), 0), NBIN - 1)
                    : NBIN - 1;
    g_bin[idx] = bin;
    atomicAdd(&g_hist[b * NBIN + bin], 1);

    float sc0 = src_cam[b * 3 + 0];
    float sc1 = src_cam[b * 3 + 1];
    float sc2 = src_cam[b * 3 + 2];
    const float* sv = src_verts + (size_t)b * NV * 3;
    g_sf[idx * 3 + 0] = make_float2(sc0 * (sv[i0 * 3 + 0] + sc1), sc0 * (sv[i0 * 3 + 1] + sc2));
    g_sf[idx * 3 + 1] = make_float2(sc0 * (sv[i1 * 3 + 0] + sc1), sc0 * (sv[i1 * 3 + 1] + sc2));
    g_sf[idx * 3 + 2] = make_float2(sc0 * (sv[i2 * 3 + 0] + sc1), sc0 * (sv[i2 * 3 + 1] + sc2));
}

// 3-phase shfl scan: 2 barriers instead of 20
__global__ __launch_bounds__(NBIN) void scan_kernel()
{
    __shared__ int wsum[32];
    int b = blockIdx.x;
    int t = threadIdx.x;
    int lane = t & 31;
    int w = t >> 5;
    int v = g_hist[b * NBIN + t];
    int s = v;
    #pragma unroll
    for (int d = 1; d < 32; d <<= 1) {
        int n = __shfl_up_sync(0xffffffffu, s, d);
        if (lane >= d) s += n;
    }
    if (lane == 31) wsum[w] = s;
    __syncthreads();
    if (w == 0) {
        int x = wsum[lane];
        int xs = x;
        #pragma unroll
        for (int d = 1; d < 32; d <<= 1) {
            int n = __shfl_up_sync(0xffffffffu, xs, d);
            if (lane >= d) xs += n;
        }
        wsum[lane] = xs - x;   // exclusive warp offsets
    }
    __syncthreads();
    g_pos[b * NBIN + t] = wsum[w] + s - v;   // exclusive prefix
}

__global__ void scatter_kernel()
{
    int idx = blockIdx.x * blockDim.x + threadIdx.x;
    if (idx >= BATCH * NF) return;
    int b = idx / NF;
    int bin = g_bin[idx];
    int pos = atomicAdd(&g_pos[b * NBIN + bin], 1);
    int dst = b * NF + pos;
    g_fa_s[dst] = g_fa[idx];
    g_fb_s[dst] = g_fb[idx];
    g_fc_s[dst] = g_fc[idx];
    g_bb_s[dst] = g_bb[idx];
    g_dd_s[dst] = g_dd[idx];
    g_zfl[dst] = (bin == 0) ? -BIGF : ((float)bin * (1.0f / 64.0f) - 8.0f);
}

__global__ __launch_bounds__(CULL) void raster_kernel()
{
    __shared__ float4 s_fa[CULL];
    __shared__ float4 s_fb[CULL];
    __shared__ float2 s_fc[CULL];
    __shared__ float4 s_dd[CULL];
    __shared__ int    s_wcnt[NWARPS];
    __shared__ float  s_zw[NWARPS];
    __shared__ float2 s_sub[NWARPS][CULL];

    const int b     = blockIdx.z;
    const int seg   = blockIdx.y;
    const int tileX = blockIdx.x & 15;
    const int tileY = blockIdx.x >> 4;
    const int tid   = threadIdx.x;
    const int lane  = tid & 31;
    const int warp  = tid >> 5;

    const int sbx = (warp & 1) * 8;
    const int sby = (warp >> 1) * 8;
    const int p0  = lane * 2;
    const int px0_i = tileX * TILE + sbx + (p0 & 7);
    const int py_i  = tileY * TILE + sby + (p0 >> 3);
    const float px0 = ((float)px0_i + 0.5f) / 256.0f * 2.0f - 1.0f;
    const float px1 = ((float)(px0_i + 1) + 0.5f) / 256.0f * 2.0f - 1.0f;
    const float py  = ((float)py_i + 0.5f) / 256.0f * 2.0f - 1.0f;

    const float tx0 = ((float)(tileX * TILE)            + 0.5f) / 256.0f * 2.0f - 1.0f;
    const float tx1 = ((float)(tileX * TILE + TILE - 1) + 0.5f) / 256.0f * 2.0f - 1.0f;
    const float ty0 = ((float)(tileY * TILE)            + 0.5f) / 256.0f * 2.0f - 1.0f;
    const float ty1 = ((float)(tileY * TILE + TILE - 1) + 0.5f) / 256.0f * 2.0f - 1.0f;
    const float cx  = 0.5f * (tx0 + tx1);
    const float cy  = 0.5f * (ty0 + ty1);
    const float hx  = 0.5f * (tx1 - tx0);
    const float hy  = 0.5f * (ty1 - ty0);

    const float scx = ((float)(tileX * TILE + sbx) + 4.0f) / 128.0f - 1.0f;
    const float scy = ((float)(tileY * TILE + sby) + 4.0f) / 128.0f - 1.0f;
    const float shx = 3.5f / 128.0f;
    const float shy = 3.5f / 128.0f;
    const float dxs = scx - cx;
    const float dys = scy - cy;

    const float4* __restrict__ fa = g_fa_s + b * NF;
    const float4* __restrict__ fb = g_fb_s + b * NF;
    const float2* __restrict__ fc = g_fc_s + b * NF;
    const float4* __restrict__ bb = g_bb_s + b * NF;
    const float2* __restrict__ dd = g_dd_s + b * NF;
    const float*  __restrict__ zfl = g_zfl + b * NF;

    unsigned long long* zb = g_zb + (size_t)b * PP;
    unsigned long long* zslot0 = zb + py_i * WW + px0_i;
    const unsigned long long* zpair = zslot0;

    float zmin0 = BIGF, zmin1 = BIGF;
    int   best0 = -1,   best1 = -1;
    float wz0 = BIGF, wz1 = BIGF;
    float gz0 = BIGF, gz1 = BIGF;
    float zmaxw = BIGF;

    const int fbeg = seg * SEGLEN;
    const int fend = min(fbeg + SEGLEN, NF);

    for (int base = fbeg; base < fend; base += CULL) {
        {
            ulonglong2 gk = *(const ulonglong2*)zpair;
            gz0 = fminf(gz0, sortable2f((unsigned int)(gk.x >> 32)));
            gz1 = fminf(gz1, sortable2f((unsigned int)(gk.y >> 32)));
            float zm = fmaxf(fminf(zmin0, gz0), fminf(zmin1, gz1));
            #pragma unroll
            for (int d = 16; d >= 1; d >>= 1)
                zm = fmaxf(zm, __shfl_xor_sync(0xffffffffu, zm, d));
            zmaxw = zm;
            if (lane == 0) s_zw[warp] = zm;
        }
        __syncthreads();
        float zmaxc = fmaxf(fmaxf(s_zw[0], s_zw[1]), fmaxf(s_zw[2], s_zw[3]));
        if (zfl[base] > zmaxc) break;

        int f = base + tid;
        bool pass = false;
        float dc = 0.0f, beta = 0.0f, gamma = 0.0f;
        if (f < fend) {
            float4 bx = bb[f];
            pass = (bx.x <= tx1) & (bx.y >= tx0) & (bx.z <= ty1) & (bx.w >= ty0);
            if (pass) {
                float4 a  = fa[f];
                float4 c4 = fb[f];
                float z2  = fc[f].x;
                float dxc = cx - c4.x;
                float dyc = cy - c4.y;
                float w0c = a.x * dxc + a.y * dyc;
                float w1c = a.z * dxc + a.w * dyc;
                float w2c = 1.0f - w0c - w1c;
                float s0  = fabsf(a.x) * hx + fabsf(a.y) * hy;
                float s1  = fabsf(a.z) * hx + fabsf(a.w) * hy;
                float s2  = fabsf(a.x + a.z) * hx + fabsf(a.y + a.w) * hy;
                float m0  = 1e-5f * (fabsf(w0c) + s0) + 1e-6f;
                float m1  = 1e-5f * (fabsf(w1c) + s1) + 1e-6f;
                float m2  = 1e-5f * (fabsf(w2c) + s2) + 1e-6f;
                pass = (w0c + s0 >= -m0) & (w1c + s1 >= -m1) & (w2c + s2 >= -m2);
                if (pass) {
                    dc = w0c * c4.z + w1c * c4.w + w2c * z2;
                    float2 g = dd[f];
                    beta = g.x; gamma = g.y;
                }
            }
        }
        unsigned m = __ballot_sync(0xffffffffu, pass);
        if (lane == 0) s_wcnt[warp] = __popc(m);
        __syncthreads();

        int off = 0;
        int cnt = 0;
        #pragma unroll
        for (int w = 0; w < NWARPS; w++) {
            int c = s_wcnt[w];
            if (w < warp) off += c;
            cnt += c;
        }
        off += __popc(m & ((1u << lane) - 1u));
        if (pass) {
            s_fa[off] = fa[f];
            s_fb[off] = fb[f];
            s_fc[off] = fc[f];
            s_dd[off] = make_float4(dc, beta, gamma, 0.0f);
        }
        __syncthreads();

        int scnt = 0;
        for (int j0 = 0; j0 < cnt; j0 += 32) {
            int j = j0 + lane;
            bool sp = false;
            float dmins = 0.0f;
            if (j < cnt) {
                float4 a  = s_fa[j];
                float2 xy = make_float2(s_fb[j].x, s_fb[j].y);
                float dxc = scx - xy.x;
                float dyc = scy - xy.y;
                float w0c = a.x * dxc + a.y * dyc;
                float w1c = a.z * dxc + a.w * dyc;
                float w2c = 1.0f - w0c - w1c;
                float s0  = fabsf(a.x) * shx + fabsf(a.y) * shy;
                float s1  = fabsf(a.z) * shx + fabsf(a.w) * shy;
                float s2  = fabsf(a.x + a.z) * shx + fabsf(a.y + a.w) * shy;
                float m0  = 1e-5f * (fabsf(w0c) + s0) + 1e-6f;
                float m1  = 1e-5f * (fabsf(w1c) + s1) + 1e-6f;
                float m2  = 1e-5f * (fabsf(w2c) + s2) + 1e-6f;
                sp = (w0c + s0 >= -m0) & (w1c + s1 >= -m1) & (w2c + s2 >= -m2);
                if (sp) {
                    float4 dv = s_dd[j];
                    float sd  = fabsf(dv.y) * shx + fabsf(dv.z) * shy;
                    float dcs = dv.x + dv.y * dxs + dv.z * dys;
                    float mg  = 1e-4f * (fabsf(dcs) + sd) + 1e-5f;
                    dmins = dcs - sd - mg;
                    sp = dmins <= zmaxw;
                }
            }
            unsigned sm = __ballot_sync(0xffffffffu, sp);
            if (sp) s_sub[warp][scnt + __popc(sm & ((1u << lane) - 1u))] =
                        make_float2(dmins, __int_as_float(j));
            scnt += __popc(sm);
        }

        for (int k = 0; k < scnt; k++) {
            if ((k & 15) == 0) {
                float zm = fmaxf(fminf(zmin0, gz0), fminf(zmin1, gz1));
                #pragma unroll
                for (int d = 16; d >= 1; d >>= 1)
                    zm = fmaxf(zm, __shfl_xor_sync(0xffffffffu, zm, d));
                zmaxw = zm;
            }
            float2 di = s_sub[warp][k];
            if (di.x > zmaxw) continue;
            int idx   = __float_as_int(di.y);
            float4 a  = s_fa[idx];
            float4 c4 = s_fb[idx];
            float2 e  = s_fc[idx];
            float dy  = py  - c4.y;
            float dx0 = px0 - c4.x;
            float dx1 = px1 - c4.x;
            float t0  = a.y * dy;
            float t1  = a.w * dy;
            float w0a = fmaf(a.x, dx0, t0);
            float w0b = fmaf(a.x, dx1, t0);
            float w1a = fmaf(a.z, dx0, t1);
            float w1b = fmaf(a.z, dx1, t1);
            float w2a = 1.0f - w0a - w1a;
            float w2b = 1.0f - w0b - w1b;
            float da  = fmaf(w0a, c4.z, fmaf(w1a, c4.w, w2a * e.x));
            float db  = fmaf(w0b, c4.z, fmaf(w1b, c4.w, w2b * e.x));
            int oa = __float_as_int(w0a) | __float_as_int(w1a) | __float_as_int(w2a);
            int ob = __float_as_int(w0b) | __float_as_int(w1b) | __float_as_int(w2b);
            if ((oa >= 0) && (da < zmin0)) { zmin0 = da; best0 = __float_as_int(e.y); }
            if ((ob >= 0) && (db < zmin1)) { zmin1 = db; best1 = __float_as_int(e.y); }
        }

        if (zmin0 < wz0) {
            wz0 = zmin0;
            unsigned long long key =
                ((unsigned long long)f2sortable(zmin0) << 32) | (unsigned int)best0;
            atomicMin(zslot0, key);
        }
        if (zmin1 < wz1) {
            wz1 = zmin1;
            unsigned long long key =
                ((unsigned long long)f2sortable(zmin1) << 32) | (unsigned int)best1;
            atomicMin(zslot0 + 1, key);
        }
        __syncthreads();
    }

    if (best0 >= 0 && zmin0 < wz0) {
        unsigned long long key =
            ((unsigned long long)f2sortable(zmin0) << 32) | (unsigned int)best0;
        atomicMin(zslot0, key);
    }
    if (best1 >= 0 && zmin1 < wz1) {
        unsigned long long key =
            ((unsigned long long)f2sortable(zmin1) << 32) | (unsigned int)best1;
        atomicMin(zslot0 + 1, key);
    }
}

// 2 pixels/thread for doubled memory-level parallelism
__global__ __launch_bounds__(256) void resolve_kernel(const float* __restrict__ src_img,
                                                      float* __restrict__ out)
{
    const int b    = blockIdx.y;
    const int pr   = blockIdx.x * 256 + threadIdx.x;   // pair index
    const int pix0 = pr * 2;
    const int px_i0 = pix0 & (WW - 1);
    const int py_i  = pix0 >> 8;

    ulonglong2 keys = *(const ulonglong2*)(g_zb + (size_t)b * PP + pix0);
    const float* img = src_img + (size_t)b * 3 * HH * WW;

    #pragma unroll
    for (int h = 0; h < 2; h++) {
        int px_i = px_i0 + h;
        unsigned long long key = h ? keys.y : keys.x;
        unsigned int face = (unsigned int)(key & 0xFFFFFFFFull);
        float px = ((float)px_i + 0.5f) / 256.0f * 2.0f - 1.0f;
        float py = ((float)py_i + 0.5f) / 256.0f * 2.0f - 1.0f;

        float fx, fy;
        if (face != 0xFFFFFFFFu) {
            int gi = b * NF + (int)face;
            float4 a  = g_fa[gi];
            float4 c4 = g_fb[gi];
            float dx = px - c4.x;
            float dy = py - c4.y;
            float w0 = fmaf(a.x, dx, a.y * dy);
            float w1 = fmaf(a.z, dx, a.w * dy);
            float w2 = 1.0f - w0 - w1;
            float2 s0 = g_sf[gi * 3 + 0];
            float2 s1 = g_sf[gi * 3 + 1];
            float2 s2 = g_sf[gi * 3 + 2];
            fx = w0 * s0.x + w1 * s1.x + w2 * s2.x;
            fy = w0 * s0.y + w1 * s1.y + w2 * s2.y;
        } else {
            fx = -2.0f;
            fy = -2.0f;
        }

        float ix = fminf(fmaxf(((fx + 1.0f) * 256.0f - 1.0f) * 0.5f, 0.0f), 255.0f);
        float iy = fminf(fmaxf(((fy + 1.0f) * 256.0f - 1.0f) * 0.5f, 0.0f), 255.0f);
        float x0f = floorf(ix);
        float y0f = floorf(iy);
        float wx = ix - x0f;
        float wy = iy - y0f;
        int x0i = (int)x0f;
        int y0i = (int)y0f;
        int x1i = min(x0i + 1, WW - 1);
        int y1i = min(y0i + 1, HH - 1);

        float wa = (1.0f - wx) * (1.0f - wy);
        float wb = wx * (1.0f - wy);
        float wc = (1.0f - wx) * wy;
        float wd = wx * wy;

        #pragma unroll
        for (int c = 0; c < 3; c++) {
            const float* p = img + (size_t)c * HH * WW;
            float Ia = p[y0i * WW + x0i];
            float Ib = p[y0i * WW + x1i];
            float Ic = p[y1i * WW + x0i];
            float Id = p[y1i * WW + x1i];
            out[(((size_t)b * 3 + c) * HH + py_i) * WW + px_i] =
                Ia * wa + Ib * wb + Ic * wc + Id * wd;
        }
    }
}

extern "C" void kernel_launch(void* const* d_in, const int* in_sizes, int n_in,
                              void* d_out, int out_size)
{
    const float* src_img   = (const float*)d_in[0];
    const float* src_cam   = (const float*)d_in[1];
    const float* src_verts = (const float*)d_in[2];
    const float* tgt_cam   = (const float*)d_in[3];
    const float* tgt_verts = (const float*)d_in[4];
    const int*   faces     = (const int*)d_in[5];
    float* out = (float*)d_out;

    int n = BATCH * NF;
    zinit_kernel<<<(BATCH * PP + 255) / 256, 256>>>();
    setup_kernel<<<(n + 255) / 256, 256>>>(src_cam, src_verts, tgt_cam, tgt_verts, faces);
    scan_kernel<<<BATCH, NBIN>>>();
    scatter_kernel<<<(n + 255) / 256, 256>>>();
    dim3 rgrid(256, NSEG, BATCH);
    raster_kernel<<<rgrid, CULL>>>();
    dim3 ggrid(PP / 512, BATCH);
    resolve_kernel<<<ggrid, 256>>>(src_img, out);
}

// round 13
// speedup vs baseline: 1.1082x; 1.0361x over previous
#include <cuda_runtime.h>

#define HH 256
#define WW 256
#define PP (HH * WW)
#define NF 13776
#define NV 6890
#define BATCH 2
#define BIGF 1000000000.0f
#define EPSF 1e-8f
#define TILE 16
#define NSEG 16
#define SEGLEN ((NF + NSEG - 1) / NSEG)
#define CULL 128
#define NWARPS 4
#define NBIN 1024

// Per-(batch,face) data by face id (resolve reads these)
__device__ float4 g_fa[BATCH * NF];
__device__ float4 g_fb[BATCH * NF];
__device__ float2 g_sf[BATCH * NF * 3];
// Sort bookkeeping
__device__ int    g_hist[BATCH * NBIN];
__device__ int    g_pos[BATCH * NBIN];
// Depth-sorted arrays (raster reads these sequentially)
__device__ float4 g_fa_s[BATCH * NF];
__device__ float4 g_fb_s[BATCH * NF];
__device__ float2 g_fc_s[BATCH * NF];
__device__ float4 g_bb_s[BATCH * NF];
__device__ float2 g_dd_s[BATCH * NF];
__device__ float  g_zfl[BATCH * NF];      // monotone bin-floor depth at sorted pos
__device__ unsigned long long g_zb[BATCH * PP];

__device__ __forceinline__ unsigned int f2sortable(float d) {
    unsigned int u = __float_as_uint(d);
    return u ^ (((unsigned int)((int)u >> 31)) | 0x80000000u);
}
__device__ __forceinline__ float sortable2f(unsigned int s) {
    unsigned int u = (s & 0x80000000u) ? (s ^ 0x80000000u) : ~s;
    return __uint_as_float(u);
}

__global__ void zinit_kernel()
{
    int i = blockIdx.x * blockDim.x + threadIdx.x;
    if (i < BATCH * PP)
        g_zb[i] = ((unsigned long long)f2sortable(BIGF) << 32) | 0xFFFFFFFFull;
    if (i < BATCH * NBIN)
        g_hist[i] = 0;
}

// Pass A: compute depth bin only, build histogram (no bulk writes)
__global__ void binhist_kernel(const float* __restrict__ tgt_cam,
                               const float* __restrict__ tgt_verts,
                               const int*   __restrict__ faces)
{
    int idx = blockIdx.x * blockDim.x + threadIdx.x;
    if (idx >= BATCH * NF) return;
    int b = idx / NF;
    int f = idx - b * NF;

    int i0 = faces[f * 3 + 0];
    int i1 = faces[f * 3 + 1];
    int i2 = faces[f * 3 + 2];

    float tc0 = tgt_cam[b * 3 + 0];
    float tc1 = tgt_cam[b * 3 + 1];
    float tc2 = tgt_cam[b * 3 + 2];
    const float* tv = tgt_verts + (size_t)b * NV * 3;

    float x0 = tc0 * (tv[i0 * 3 + 0] + tc1);
    float y0 = -(tc0 * (tv[i0 * 3 + 1] + tc2));
    float z0 = tv[i0 * 3 + 2];
    float x1 = tc0 * (tv[i1 * 3 + 0] + tc1);
    float y1 = -(tc0 * (tv[i1 * 3 + 1] + tc2));
    float z1 = tv[i1 * 3 + 2];
    float x2 = tc0 * (tv[i2 * 3 + 0] + tc1);
    float y2 = -(tc0 * (tv[i2 * 3 + 1] + tc2));
    float z2 = tv[i2 * 3 + 2];

    float denom = (y1 - y2) * (x0 - x2) + (x2 - x1) * (y0 - y2);
    bool valid = fabsf(denom) >= EPSF;

    float zs = fminf(z0, fminf(z1, z2));
    float safe = zs - (1e-5f * fabsf(zs) + 1e-6f);
    int bin = valid ? min(max((int)floorf((safe + 8.0f) * 64.0f), 0), NBIN - 1)
                    : NBIN - 1;
    atomicAdd(&g_hist[b * NBIN + bin], 1);
}

// 3-phase shfl scan (2 barriers)
__global__ __launch_bounds__(NBIN) void scan_kernel()
{
    __shared__ int wsum[32];
    int b = blockIdx.x;
    int t = threadIdx.x;
    int lane = t & 31;
    int w = t >> 5;
    int v = g_hist[b * NBIN + t];
    int s = v;
    #pragma unroll
    for (int d = 1; d < 32; d <<= 1) {
        int n = __shfl_up_sync(0xffffffffu, s, d);
        if (lane >= d) s += n;
    }
    if (lane == 31) wsum[w] = s;
    __syncthreads();
    if (w == 0) {
        int x = wsum[lane];
        int xs = x;
        #pragma unroll
        for (int d = 1; d < 32; d <<= 1) {
            int n = __shfl_up_sync(0xffffffffu, xs, d);
            if (lane >= d) xs += n;
        }
        wsum[lane] = xs - x;
    }
    __syncthreads();
    g_pos[b * NBIN + t] = wsum[w] + s - v;   // exclusive prefix
}

// Pass B: full setup; raster data written directly into sorted slots
__global__ void setup_kernel(const float* __restrict__ src_cam,
                             const float* __restrict__ src_verts,
                             const float* __restrict__ tgt_cam,
                             const float* __restrict__ tgt_verts,
                             const int*   __restrict__ faces)
{
    int idx = blockIdx.x * blockDim.x + threadIdx.x;
    if (idx >= BATCH * NF) return;
    int b = idx / NF;
    int f = idx - b * NF;

    int i0 = faces[f * 3 + 0];
    int i1 = faces[f * 3 + 1];
    int i2 = faces[f * 3 + 2];

    float tc0 = tgt_cam[b * 3 + 0];
    float tc1 = tgt_cam[b * 3 + 1];
    float tc2 = tgt_cam[b * 3 + 2];
    const float* tv = tgt_verts + (size_t)b * NV * 3;

    float x0 = tc0 * (tv[i0 * 3 + 0] + tc1);
    float y0 = -(tc0 * (tv[i0 * 3 + 1] + tc2));
    float z0 = tv[i0 * 3 + 2];
    float x1 = tc0 * (tv[i1 * 3 + 0] + tc1);
    float y1 = -(tc0 * (tv[i1 * 3 + 1] + tc2));
    float z1 = tv[i1 * 3 + 2];
    float x2 = tc0 * (tv[i2 * 3 + 0] + tc1);
    float y2 = -(tc0 * (tv[i2 * 3 + 1] + tc2));
    float z2 = tv[i2 * 3 + 2];

    float denom = (y1 - y2) * (x0 - x2) + (x2 - x1) * (y0 - y2);
    bool valid = fabsf(denom) >= EPSF;
    float inv = 1.0f / (valid ? denom : 1.0f);

    float ax = (y1 - y2) * inv, ay = (x2 - x1) * inv;
    float az = (y2 - y0) * inv, aw = (x0 - x2) * inv;
    float4 fa4 = make_float4(ax, ay, az, aw);
    float4 fb4 = make_float4(x2, y2, z0, z1);
    g_fa[idx] = fa4;
    g_fb[idx] = fb4;
    float beta  = ax * z0 + az * z1 - (ax + az) * z2;
    float gamma = ay * z0 + aw * z1 - (ay + aw) * z2;

    const float pad = 2.0f / 256.0f;
    float xmn = fminf(x0, fminf(x1, x2)) - pad;
    float xmx = fmaxf(x0, fmaxf(x1, x2)) + pad;
    float ymn = fminf(y0, fminf(y1, y2)) - pad;
    float ymx = fmaxf(y0, fmaxf(y1, y2)) + pad;
    if (!valid) { xmn = 1e30f; xmx = -1e30f; ymn = 1e30f; ymx = -1e30f; }

    // depth bin (identical to pass A) -> sorted slot
    float zs = fminf(z0, fminf(z1, z2));
    float safe = zs - (1e-5f * fabsf(zs) + 1e-6f);
    int bin = valid ? min(max((int)floorf((safe + 8.0f) * 64.0f), 0), NBIN - 1)
                    : NBIN - 1;
    int pos = atomicAdd(&g_pos[b * NBIN + bin], 1);
    int dst = b * NF + pos;
    g_fa_s[dst] = fa4;
    g_fb_s[dst] = fb4;
    g_fc_s[dst] = make_float2(z2, __int_as_float(f));
    g_bb_s[dst] = make_float4(xmn, xmx, ymn, ymx);
    g_dd_s[dst] = make_float2(beta, gamma);
    g_zfl[dst]  = (bin == 0) ? -BIGF : ((float)bin * (1.0f / 64.0f) - 8.0f);

    float sc0 = src_cam[b * 3 + 0];
    float sc1 = src_cam[b * 3 + 1];
    float sc2 = src_cam[b * 3 + 2];
    const float* sv = src_verts + (size_t)b * NV * 3;
    g_sf[idx * 3 + 0] = make_float2(sc0 * (sv[i0 * 3 + 0] + sc1), sc0 * (sv[i0 * 3 + 1] + sc2));
    g_sf[idx * 3 + 1] = make_float2(sc0 * (sv[i1 * 3 + 0] + sc1), sc0 * (sv[i1 * 3 + 1] + sc2));
    g_sf[idx * 3 + 2] = make_float2(sc0 * (sv[i2 * 3 + 0] + sc1), sc0 * (sv[i2 * 3 + 1] + sc2));
}

__global__ __launch_bounds__(CULL) void raster_kernel()
{
    __shared__ float4 s_fa[CULL];
    __shared__ float4 s_fb[CULL];
    __shared__ float2 s_fc[CULL];
    __shared__ float4 s_dd[CULL];
    __shared__ int    s_wcnt[NWARPS];
    __shared__ float  s_zw[NWARPS];
    __shared__ float2 s_sub[NWARPS][CULL];

    const int b     = blockIdx.z;
    const int seg   = blockIdx.y;
    const int tileX = blockIdx.x & 15;
    const int tileY = blockIdx.x >> 4;
    const int tid   = threadIdx.x;
    const int lane  = tid & 31;
    const int warp  = tid >> 5;

    const int sbx = (warp & 1) * 8;
    const int sby = (warp >> 1) * 8;
    const int p0  = lane * 2;
    const int px0_i = tileX * TILE + sbx + (p0 & 7);
    const int py_i  = tileY * TILE + sby + (p0 >> 3);
    const float px0 = ((float)px0_i + 0.5f) / 256.0f * 2.0f - 1.0f;
    const float px1 = ((float)(px0_i + 1) + 0.5f) / 256.0f * 2.0f - 1.0f;
    const float py  = ((float)py_i + 0.5f) / 256.0f * 2.0f - 1.0f;

    const float tx0 = ((float)(tileX * TILE)            + 0.5f) / 256.0f * 2.0f - 1.0f;
    const float tx1 = ((float)(tileX * TILE + TILE - 1) + 0.5f) / 256.0f * 2.0f - 1.0f;
    const float ty0 = ((float)(tileY * TILE)            + 0.5f) / 256.0f * 2.0f - 1.0f;
    const float ty1 = ((float)(tileY * TILE + TILE - 1) + 0.5f) / 256.0f * 2.0f - 1.0f;
    const float cx  = 0.5f * (tx0 + tx1);
    const float cy  = 0.5f * (ty0 + ty1);
    const float hx  = 0.5f * (tx1 - tx0);
    const float hy  = 0.5f * (ty1 - ty0);

    const float scx = ((float)(tileX * TILE + sbx) + 4.0f) / 128.0f - 1.0f;
    const float scy = ((float)(tileY * TILE + sby) + 4.0f) / 128.0f - 1.0f;
    const float shx = 3.5f / 128.0f;
    const float shy = 3.5f / 128.0f;
    const float dxs = scx - cx;
    const float dys = scy - cy;

    const float4* __restrict__ fa = g_fa_s + b * NF;
    const float4* __restrict__ fb = g_fb_s + b * NF;
    const float2* __restrict__ fc = g_fc_s + b * NF;
    const float4* __restrict__ bb = g_bb_s + b * NF;
    const float2* __restrict__ dd = g_dd_s + b * NF;
    const float*  __restrict__ zfl = g_zfl + b * NF;

    unsigned long long* zb = g_zb + (size_t)b * PP;
    unsigned long long* zslot0 = zb + py_i * WW + px0_i;
    const unsigned long long* zpair = zslot0;

    float zmin0 = BIGF, zmin1 = BIGF;
    int   best0 = -1,   best1 = -1;
    float wz0 = BIGF, wz1 = BIGF;
    float gz0 = BIGF, gz1 = BIGF;
    float zmaxw = BIGF;

    const int fbeg = seg * SEGLEN;
    const int fend = min(fbeg + SEGLEN, NF);

    for (int base = fbeg; base < fend; base += CULL) {
        {
            ulonglong2 gk = *(const ulonglong2*)zpair;
            gz0 = fminf(gz0, sortable2f((unsigned int)(gk.x >> 32)));
            gz1 = fminf(gz1, sortable2f((unsigned int)(gk.y >> 32)));
            float zm = fmaxf(fminf(zmin0, gz0), fminf(zmin1, gz1));
            #pragma unroll
            for (int d = 16; d >= 1; d >>= 1)
                zm = fmaxf(zm, __shfl_xor_sync(0xffffffffu, zm, d));
            zmaxw = zm;
            if (lane == 0) s_zw[warp] = zm;
        }
        __syncthreads();
        float zmaxc = fmaxf(fmaxf(s_zw[0], s_zw[1]), fmaxf(s_zw[2], s_zw[3]));
        if (zfl[base] > zmaxc) break;

        int f = base + tid;
        bool pass = false;
        float dc = 0.0f, beta = 0.0f, gamma = 0.0f;
        if (f < fend) {
            float4 bx = bb[f];
            pass = (bx.x <= tx1) & (bx.y >= tx0) & (bx.z <= ty1) & (bx.w >= ty0);
            if (pass) {
                float4 a  = fa[f];
                float4 c4 = fb[f];
                float z2  = fc[f].x;
                float dxc = cx - c4.x;
                float dyc = cy - c4.y;
                float w0c = a.x * dxc + a.y * dyc;
                float w1c = a.z * dxc + a.w * dyc;
                float w2c = 1.0f - w0c - w1c;
                float s0  = fabsf(a.x) * hx + fabsf(a.y) * hy;
                float s1  = fabsf(a.z) * hx + fabsf(a.w) * hy;
                float s2  = fabsf(a.x + a.z) * hx + fabsf(a.y + a.w) * hy;
                float m0  = 1e-5f * (fabsf(w0c) + s0) + 1e-6f;
                float m1  = 1e-5f * (fabsf(w1c) + s1) + 1e-6f;
                float m2  = 1e-5f * (fabsf(w2c) + s2) + 1e-6f;
                pass = (w0c + s0 >= -m0) & (w1c + s1 >= -m1) & (w2c + s2 >= -m2);
                if (pass) {
                    dc = w0c * c4.z + w1c * c4.w + w2c * z2;
                    float2 g = dd[f];
                    beta = g.x; gamma = g.y;
                }
            }
        }
        unsigned m = __ballot_sync(0xffffffffu, pass);
        if (lane == 0) s_wcnt[warp] = __popc(m);
        __syncthreads();

        int off = 0;
        int cnt = 0;
        #pragma unroll
        for (int w = 0; w < NWARPS; w++) {
            int c = s_wcnt[w];
            if (w < warp) off += c;
            cnt += c;
        }
        off += __popc(m & ((1u << lane) - 1u));
        if (pass) {
            s_fa[off] = fa[f];
            s_fb[off] = fb[f];
            s_fc[off] = fc[f];
            s_dd[off] = make_float4(dc, beta, gamma, 0.0f);
        }
        __syncthreads();

        int scnt = 0;
        for (int j0 = 0; j0 < cnt; j0 += 32) {
            int j = j0 + lane;
            bool sp = false;
            float dmins = 0.0f;
            if (j < cnt) {
                float4 a  = s_fa[j];
                float2 xy = make_float2(s_fb[j].x, s_fb[j].y);
                float dxc = scx - xy.x;
                float dyc = scy - xy.y;
                float w0c = a.x * dxc + a.y * dyc;
                float w1c = a.z * dxc + a.w * dyc;
                float w2c = 1.0f - w0c - w1c;
                float s0  = fabsf(a.x) * shx + fabsf(a.y) * shy;
                float s1  = fabsf(a.z) * shx + fabsf(a.w) * shy;
                float s2  = fabsf(a.x + a.z) * shx + fabsf(a.y + a.w) * shy;
                float m0  = 1e-5f * (fabsf(w0c) + s0) + 1e-6f;
                float m1  = 1e-5f * (fabsf(w1c) + s1) + 1e-6f;
                float m2  = 1e-5f * (fabsf(w2c) + s2) + 1e-6f;
                sp = (w0c + s0 >= -m0) & (w1c + s1 >= -m1) & (w2c + s2 >= -m2);
                if (sp) {
                    float4 dv = s_dd[j];
                    float sd  = fabsf(dv.y) * shx + fabsf(dv.z) * shy;
                    float dcs = dv.x + dv.y * dxs + dv.z * dys;
                    float mg  = 1e-4f * (fabsf(dcs) + sd) + 1e-5f;
                    dmins = dcs - sd - mg;
                    sp = dmins <= zmaxw;
                }
            }
            unsigned sm = __ballot_sync(0xffffffffu, sp);
            if (sp) s_sub[warp][scnt + __popc(sm & ((1u << lane) - 1u))] =
                        make_float2(dmins, __int_as_float(j));
            scnt += __popc(sm);
        }

        for (int k = 0; k < scnt; k++) {
            if ((k & 15) == 0) {
                float zm = fmaxf(fminf(zmin0, gz0), fminf(zmin1, gz1));
                #pragma unroll
                for (int d = 16; d >= 1; d >>= 1)
                    zm = fmaxf(zm, __shfl_xor_sync(0xffffffffu, zm, d));
                zmaxw = zm;
            }
            float2 di = s_sub[warp][k];
            if (di.x > zmaxw) continue;
            int idx   = __float_as_int(di.y);
            float4 a  = s_fa[idx];
            float4 c4 = s_fb[idx];
            float2 e  = s_fc[idx];
            float dy  = py  - c4.y;
            float dx0 = px0 - c4.x;
            float dx1 = px1 - c4.x;
            float t0  = a.y * dy;
            float t1  = a.w * dy;
            float w0a = fmaf(a.x, dx0, t0);
            float w0b = fmaf(a.x, dx1, t0);
            float w1a = fmaf(a.z, dx0, t1);
            float w1b = fmaf(a.z, dx1, t1);
            float w2a = 1.0f - w0a - w1a;
            float w2b = 1.0f - w0b - w1b;
            float da  = fmaf(w0a, c4.z, fmaf(w1a, c4.w, w2a * e.x));
            float db  = fmaf(w0b, c4.z, fmaf(w1b, c4.w, w2b * e.x));
            int oa = __float_as_int(w0a) | __float_as_int(w1a) | __float_as_int(w2a);
            int ob = __float_as_int(w0b) | __float_as_int(w1b) | __float_as_int(w2b);
            if ((oa >= 0) && (da < zmin0)) { zmin0 = da; best0 = __float_as_int(e.y); }
            if ((ob >= 0) && (db < zmin1)) { zmin1 = db; best1 = __float_as_int(e.y); }
        }

        if (zmin0 < wz0) {
            wz0 = zmin0;
            unsigned long long key =
                ((unsigned long long)f2sortable(zmin0) << 32) | (unsigned int)best0;
            atomicMin(zslot0, key);
        }
        if (zmin1 < wz1) {
            wz1 = zmin1;
            unsigned long long key =
                ((unsigned long long)f2sortable(zmin1) << 32) | (unsigned int)best1;
            atomicMin(zslot0 + 1, key);
        }
        __syncthreads();
    }

    if (best0 >= 0 && zmin0 < wz0) {
        unsigned long long key =
            ((unsigned long long)f2sortable(zmin0) << 32) | (unsigned int)best0;
        atomicMin(zslot0, key);
    }
    if (best1 >= 0 && zmin1 < wz1) {
        unsigned long long key =
            ((unsigned long long)f2sortable(zmin1) << 32) | (unsigned int)best1;
        atomicMin(zslot0 + 1, key);
    }
}

// 2 pixels/thread for doubled memory-level parallelism
__global__ __launch_bounds__(256) void resolve_kernel(const float* __restrict__ src_img,
                                                      float* __restrict__ out)
{
    const int b    = blockIdx.y;
    const int pr   = blockIdx.x * 256 + threadIdx.x;   // pair index
    const int pix0 = pr * 2;
    const int px_i0 = pix0 & (WW - 1);
    const int py_i  = pix0 >> 8;

    ulonglong2 keys = *(const ulonglong2*)(g_zb + (size_t)b * PP + pix0);
    const float* img = src_img + (size_t)b * 3 * HH * WW;

    #pragma unroll
    for (int h = 0; h < 2; h++) {
        int px_i = px_i0 + h;
        unsigned long long key = h ? keys.y : keys.x;
        unsigned int face = (unsigned int)(key & 0xFFFFFFFFull);
        float px = ((float)px_i + 0.5f) / 256.0f * 2.0f - 1.0f;
        float py = ((float)py_i + 0.5f) / 256.0f * 2.0f - 1.0f;

        float fx, fy;
        if (face != 0xFFFFFFFFu) {
            int gi = b * NF + (int)face;
            float4 a  = g_fa[gi];
            float4 c4 = g_fb[gi];
            float dx = px - c4.x;
            float dy = py - c4.y;
            float w0 = fmaf(a.x, dx, a.y * dy);
            float w1 = fmaf(a.z, dx, a.w * dy);
            float w2 = 1.0f - w0 - w1;
            float2 s0 = g_sf[gi * 3 + 0];
            float2 s1 = g_sf[gi * 3 + 1];
            float2 s2 = g_sf[gi * 3 + 2];
            fx = w0 * s0.x + w1 * s1.x + w2 * s2.x;
            fy = w0 * s0.y + w1 * s1.y + w2 * s2.y;
        } else {
            fx = -2.0f;
            fy = -2.0f;
        }

        float ix = fminf(fmaxf(((fx + 1.0f) * 256.0f - 1.0f) * 0.5f, 0.0f), 255.0f);
        float iy = fminf(fmaxf(((fy + 1.0f) * 256.0f - 1.0f) * 0.5f, 0.0f), 255.0f);
        float x0f = floorf(ix);
        float y0f = floorf(iy);
        float wx = ix - x0f;
        float wy = iy - y0f;
        int x0i = (int)x0f;
        int y0i = (int)y0f;
        int x1i = min(x0i + 1, WW - 1);
        int y1i = min(y0i + 1, HH - 1);

        float wa = (1.0f - wx) * (1.0f - wy);
        float wb = wx * (1.0f - wy);
        float wc = (1.0f - wx) * wy;
        float wd = wx * wy;

        #pragma unroll
        for (int c = 0; c < 3; c++) {
            const float* p = img + (size_t)c * HH * WW;
            float Ia = p[y0i * WW + x0i];
            float Ib = p[y0i * WW + x1i];
            float Ic = p[y1i * WW + x0i];
            float Id = p[y1i * WW + x1i];
            out[(((size_t)b * 3 + c) * HH + py_i) * WW + px_i] =
                Ia * wa + Ib * wb + Ic * wc + Id * wd;
        }
    }
}

extern "C" void kernel_launch(void* const* d_in, const int* in_sizes, int n_in,
                              void* d_out, int out_size)
{
    const float* src_img   = (const float*)d_in[0];
    const float* src_cam   = (const float*)d_in[1];
    const float* src_verts = (const float*)d_in[2];
    const float* tgt_cam   = (const float*)d_in[3];
    const float* tgt_verts = (const float*)d_in[4];
    const int*   faces     = (const int*)d_in[5];
    float* out = (float*)d_out;

    int n = BATCH * NF;
    zinit_kernel<<<(BATCH * PP + 255) / 256, 256>>>();
    binhist_kernel<<<(n + 255) / 256, 256>>>(tgt_cam, tgt_verts, faces);
    scan_kernel<<<BATCH, NBIN>>>();
    setup_kernel<<<(n + 255) / 256, 256>>>(src_cam, src_verts, tgt_cam, tgt_verts, faces);
    dim3 rgrid(256, NSEG, BATCH);
    raster_kernel<<<rgrid, CULL>>>();
    dim3 ggrid(PP / 512, BATCH);
    resolve_kernel<<<ggrid, 256>>>(src_img, out);
}